// round 11
// baseline (speedup 1.0000x reference)
#include <cuda_runtime.h>
#include <cstdint>

#define D_MODEL 1024
#define NH      16
#define DH      64
#define BATCH   2
#define SEQ     2048
#define MTOT    (BATCH*SEQ)   // 4096
#define KDIM    1024

// ---------------- scratch (allocation-free) ----------------
__device__ float g_qh[(size_t)BATCH*NH*SEQ*DH];     // [b,h,s,dh]  tf32-pre-rounded
__device__ float g_kh[(size_t)BATCH*NH*SEQ*DH];
__device__ float g_vh[(size_t)BATCH*NH*SEQ*DH];
__device__ float g_attn[(size_t)BATCH*SEQ*D_MODEL]; // [b,s,h*dh]  tf32-pre-rounded

// =====================================================================
// helpers
// =====================================================================
__device__ __forceinline__ uint32_t f2tf32(float f) {
    uint32_t r;
    asm("cvt.rna.tf32.f32 %0, %1;" : "=r"(r) : "f"(f));
    return r;
}
__device__ __forceinline__ float f2tf32f(float f) { return __uint_as_float(f2tf32(f)); }

// fast exponential: single MUFU.EX2 (2-ulp approx; -20000 -> +0)
__device__ __forceinline__ float fex2(float x) {
    float r;
    asm("ex2.approx.f32 %0, %1;" : "=f"(r) : "f"(x));
    return r;
}

// D += A(16x8,row) * B(8x8,col)  tf32
__device__ __forceinline__ void mma_tf32(float c[4], const uint32_t a[4], const uint32_t b[2]) {
    asm volatile(
        "mma.sync.aligned.m16n8k8.row.col.f32.tf32.tf32.f32 "
        "{%0,%1,%2,%3}, {%4,%5,%6,%7}, {%8,%9}, {%0,%1,%2,%3};"
        : "+f"(c[0]), "+f"(c[1]), "+f"(c[2]), "+f"(c[3])
        : "r"(a[0]), "r"(a[1]), "r"(a[2]), "r"(a[3]), "r"(b[0]), "r"(b[1]));
}

// =====================================================================
// GEMM mainloop (tf32 mma.sync) — proven version, unchanged
// =====================================================================
#define GBK  32
#define ASTR 36   // BK + 4 pad

__device__ __forceinline__ void gemm_core(
    const float* __restrict__ gA, const float* __restrict__ gB,
    uint32_t* smA, uint32_t* smB, float acc[2][8][4])
{
    const int tid = threadIdx.x, wid = tid >> 5, lane = tid & 31;
    const int g = lane >> 2, tig = lane & 3;
    const int wm = wid >> 1, wn = wid & 1;

    int srow[4];
    const int scol = (tid & 7) * 4;
#pragma unroll
    for (int r = 0; r < 4; ++r) srow[r] = (tid + r*256) >> 3;

    float4 pa[4], pb[4];
#pragma unroll
    for (int r = 0; r < 4; ++r) {
        pa[r] = *(const float4*)(gA + (size_t)srow[r]*KDIM + scol);
        pb[r] = *(const float4*)(gB + (size_t)srow[r]*KDIM + scol);
    }

    const int NKT = KDIM / GBK;   // 32
    for (int kt = 0; kt < NKT; ++kt) {
        __syncthreads();
#pragma unroll
        for (int r = 0; r < 4; ++r) {
            uint32_t* pA = smA + srow[r]*ASTR + scol;
            pA[0]=f2tf32(pa[r].x); pA[1]=f2tf32(pa[r].y); pA[2]=f2tf32(pa[r].z); pA[3]=f2tf32(pa[r].w);
            uint32_t* pB = smB + srow[r]*ASTR + scol;
            pB[0]=f2tf32(pb[r].x); pB[1]=f2tf32(pb[r].y); pB[2]=f2tf32(pb[r].z); pB[3]=f2tf32(pb[r].w);
        }
        __syncthreads();
        if (kt + 1 < NKT) {
            const int k1 = (kt + 1) * GBK;
#pragma unroll
            for (int r = 0; r < 4; ++r) {
                pa[r] = *(const float4*)(gA + (size_t)srow[r]*KDIM + k1 + scol);
                pb[r] = *(const float4*)(gB + (size_t)srow[r]*KDIM + k1 + scol);
            }
        }
#pragma unroll
        for (int ks = 0; ks < 4; ++ks) {
            uint32_t af[2][4];
#pragma unroll
            for (int mt = 0; mt < 2; ++mt) {
                const int mr = wm*32 + mt*16 + g;
                af[mt][0] = smA[mr*ASTR     + ks*8 + tig];
                af[mt][1] = smA[(mr+8)*ASTR + ks*8 + tig];
                af[mt][2] = smA[mr*ASTR     + ks*8 + tig + 4];
                af[mt][3] = smA[(mr+8)*ASTR + ks*8 + tig + 4];
            }
#pragma unroll
            for (int nt = 0; nt < 8; ++nt) {
                const int nr = wn*64 + nt*8 + g;
                uint32_t bf[2];
                bf[0] = smB[nr*ASTR + ks*8 + tig];
                bf[1] = smB[nr*ASTR + ks*8 + tig + 4];
                mma_tf32(acc[0][nt], af[0], bf);
                mma_tf32(acc[1][nt], af[1], bf);
            }
        }
    }
}

// ---- fused Q/K/V projection (grid.z selects), scatter to head layout ----
__global__ __launch_bounds__(256, 2) void proj_gemm(
    const float* __restrict__ xq, const float* __restrict__ xk, const float* __restrict__ xv,
    const float* __restrict__ Wq, const float* __restrict__ Wk, const float* __restrict__ Wv,
    const float* __restrict__ bq, const float* __restrict__ bk, const float* __restrict__ bv)
{
    __shared__ uint32_t smA[128*ASTR];
    __shared__ uint32_t smB[128*ASTR];
    const int z = blockIdx.z;
    const float* X    = (z == 0) ? xq : (z == 1) ? xk : xv;
    const float* W    = (z == 0) ? Wq : (z == 1) ? Wk : Wv;
    const float* bias = (z == 0) ? bq : (z == 1) ? bk : bv;
    float* out        = (z == 0) ? g_qh : (z == 1) ? g_kh : g_vh;

    const int m0 = blockIdx.y * 128, n0 = blockIdx.x * 128;
    float acc[2][8][4] = {};
    gemm_core(X + (size_t)m0*KDIM, W + (size_t)n0*KDIM, smA, smB, acc);

    const int tid = threadIdx.x, wid = tid >> 5, lane = tid & 31;
    const int g = lane >> 2, tig = lane & 3;
    const int wm = wid >> 1, wn = wid & 1;
#pragma unroll
    for (int mt = 0; mt < 2; ++mt) {
        const int m = m0 + wm*32 + mt*16 + g;
        const int bi = m >> 11, s = m & (SEQ - 1);
#pragma unroll
        for (int nt = 0; nt < 8; ++nt) {
            const int n = n0 + wn*64 + nt*8 + 2*tig;
            const float2 bv2 = *(const float2*)(bias + n);
            float2 v0 = { f2tf32f(acc[mt][nt][0] + bv2.x), f2tf32f(acc[mt][nt][1] + bv2.y) };
            float2 v1 = { f2tf32f(acc[mt][nt][2] + bv2.x), f2tf32f(acc[mt][nt][3] + bv2.y) };
            const int h = n >> 6, d = n & 63;
            float* base = out + (((size_t)bi*NH + h)*SEQ) * DH + d;
            *(float2*)(base + (size_t)s*DH)     = v0;
            *(float2*)(base + (size_t)(s+8)*DH) = v1;
        }
    }
}

// ---- output projection: d_out = g_attn @ Wo^T + bo (unchanged) ----
__global__ __launch_bounds__(256, 2) void out_gemm(
    const float* __restrict__ Wo, const float* __restrict__ bo, float* __restrict__ out)
{
    __shared__ uint32_t smA[128*ASTR];
    __shared__ uint32_t smB[128*ASTR];
    const int m0 = blockIdx.y * 128, n0 = blockIdx.x * 128;
    float acc[2][8][4] = {};
    gemm_core(g_attn + (size_t)m0*KDIM, Wo + (size_t)n0*KDIM, smA, smB, acc);

    const int tid = threadIdx.x, wid = tid >> 5, lane = tid & 31;
    const int g = lane >> 2, tig = lane & 3;
    const int wm = wid >> 1, wn = wid & 1;
#pragma unroll
    for (int mt = 0; mt < 2; ++mt) {
        const int m = m0 + wm*32 + mt*16 + g;
#pragma unroll
        for (int nt = 0; nt < 8; ++nt) {
            const int n = n0 + wn*64 + nt*8 + 2*tig;
            const float2 bv2 = *(const float2*)(bo + n);
            float2 v0 = { acc[mt][nt][0] + bv2.x, acc[mt][nt][1] + bv2.y };
            float2 v1 = { acc[mt][nt][2] + bv2.x, acc[mt][nt][3] + bv2.y };
            *(float2*)(out + (size_t)m*D_MODEL + n)     = v0;
            *(float2*)(out + (size_t)(m+8)*D_MODEL + n) = v1;
        }
    }
}

// =====================================================================
// Flash attention: MUFU ex2 + pair-packed smem (all fragment loads LDS.64)
//   Pack: within each 8-col K group, col w -> word 2*(w&3) + (w>>2),
//   so fragment pairs (t, t+4) are adjacent words, affine addresses.
//   Qs/Ks/Ps stride 72; Vs row-pair packed (rows j, j+4 adjacent), stride 136.
//   P stored as RAW fp32 (tf32 mma truncates low mantissa bits).
// =====================================================================
#define SSTR 72
#define VSTR 136
#define KS_OFFW (128*SSTR)
#define PS_OFFW (KS_OFFW + 64*SSTR)
#define VS_OFFW (PS_OFFW + 128*SSTR)
#define ATTN_SMEM_BYTES ((VS_OFFW + 32*VSTR) * 4)
#define LOG2E    1.4426950408889634f
#define SCL_L2E  (0.125f * LOG2E)
#define FIXSHIFT 16.0f
#define MSKVAL   (-20000.0f)

__global__ __launch_bounds__(256, 2) void attn_mma(const int* __restrict__ mask)
{
    extern __shared__ uint32_t sm[];
    uint32_t* Qs = sm;                  // [128][72] pair-packed
    uint32_t* Ks = sm + KS_OFFW;        // [64][72]  pair-packed
    uint32_t* Ps = sm + PS_OFFW;        // [128][72] pair-packed
    uint32_t* Vs = sm + VS_OFFW;        // [32 pair-rows][136]

    const int qt = blockIdx.x, h = blockIdx.y, b = blockIdx.z;
    const int tid = threadIdx.x, wid = tid >> 5, lane = tid & 31;
    const int g = lane >> 2, tig = lane & 3;

    const size_t bh = ((size_t)b*NH + h)*SEQ*DH;
    const uint32_t* Qg = (const uint32_t*)g_qh + bh + (size_t)qt*128*DH;
    const uint32_t* Kg = (const uint32_t*)g_kh + bh;
    const uint32_t* Vg = (const uint32_t*)g_vh + bh;

    // stage Q packed (raw pre-rounded bits): 2048 uint4 slots / 256 thr = 8 each
#pragma unroll
    for (int r = 0; r < 8; ++r) {
        const int slot = tid + r*256;
        const int row = slot >> 4, c0 = (slot & 15) * 4;
        const uint4 v = *(const uint4*)(Qg + (size_t)row*DH + c0);
        uint32_t* p = Qs + row*SSTR + ((c0 >> 3) << 3) + ((c0 >> 2) & 1);
        p[0]=v.x; p[2]=v.y; p[4]=v.z; p[6]=v.w;
    }

    const int r0 = wid*16 + g;
    float lsum0 = 0.f, lsum1 = 0.f;
    float o[8][4];
#pragma unroll
    for (int nt = 0; nt < 8; ++nt)
#pragma unroll
        for (int i = 0; i < 4; ++i) o[nt][i] = 0.f;

    const int qrow0 = qt*128 + r0;
    const int* mrow0 = mask + ((size_t)b*SEQ + qrow0)*SEQ;
    const int* mrow1 = mrow0 + 8*SEQ;

    // per-thread staging slots (4 rows of the kv tile)
    int krow[4];
    const int kc0 = (tid & 15) * 4;
#pragma unroll
    for (int r = 0; r < 4; ++r) krow[r] = (tid + r*256) >> 4;

    // prefetch kv tile 0 (raw bits)
    uint4 pk[4], pv[4];
#pragma unroll
    for (int r = 0; r < 4; ++r) {
        pk[r] = *(const uint4*)(Kg + (size_t)krow[r]*DH + kc0);
        pv[r] = *(const uint4*)(Vg + (size_t)krow[r]*DH + kc0);
    }

    // P store word offsets for this lane (cols 2tig, 2tig+1 within a group)
    const int pw0 = (tig & 1)*4 + (tig >> 1);
    const int pw1 = pw0 + 2;

    const int NT = SEQ/64;
    for (int kt = 0; kt < NT; ++kt) {
        __syncthreads();   // prev tile fully consumed (and Q staged on kt=0)
        // store prefetched K (pair-packed) and V (row-pair packed)
#pragma unroll
        for (int r = 0; r < 4; ++r) {
            const int row = krow[r];
            uint32_t* pks = Ks + row*SSTR + ((kc0 >> 3) << 3) + ((kc0 >> 2) & 1);
            pks[0]=pk[r].x; pks[2]=pk[r].y; pks[4]=pk[r].z; pks[6]=pk[r].w;
            const int pr   = ((row >> 3) << 2) + (row & 3);   // pair-row
            const int elem = (row >> 2) & 1;
            uint32_t* pvs = Vs + pr*VSTR + kc0*2 + elem;
            pvs[0]=pv[r].x; pvs[2]=pv[r].y; pvs[4]=pv[r].z; pvs[6]=pv[r].w;
        }
        __syncthreads();
        if (kt + 1 < NT) {
            const uint32_t* Kn = Kg + (size_t)(kt+1)*64*DH;
            const uint32_t* Vn = Vg + (size_t)(kt+1)*64*DH;
#pragma unroll
            for (int r = 0; r < 4; ++r) {
                pk[r] = *(const uint4*)(Kn + (size_t)krow[r]*DH + kc0);
                pv[r] = *(const uint4*)(Vn + (size_t)krow[r]*DH + kc0);
            }
        }

        // S = Q K^T  (16 rows x 64 keys per warp); all frags via LDS.64
        float s[8][4];
#pragma unroll
        for (int nt = 0; nt < 8; ++nt) { s[nt][0]=0.f; s[nt][1]=0.f; s[nt][2]=0.f; s[nt][3]=0.f; }
#pragma unroll
        for (int ks = 0; ks < 8; ++ks) {
            const int fo = ks*8 + 2*tig;
            const uint2 qlo = *(const uint2*)&Qs[r0*SSTR + fo];
            const uint2 qhi = *(const uint2*)&Qs[(r0+8)*SSTR + fo];
            const uint32_t aQ[4] = { qlo.x, qhi.x, qlo.y, qhi.y };
#pragma unroll
            for (int nt = 0; nt < 8; ++nt) {
                const uint2 kb = *(const uint2*)&Ks[(nt*8+g)*SSTR + fo];
                const uint32_t bf[2] = { kb.x, kb.y };
                mma_tf32(s[nt], aQ, bf);
            }
        }

        // mask + fixed-shift MUFU ex2; lane-local sums; P -> smem RAW fp32
#pragma unroll
        for (int nt = 0; nt < 8; ++nt) {
            const int c = kt*64 + nt*8 + 2*tig;
            const int2 mv0 = *(const int2*)(mrow0 + c);
            const int2 mv1 = *(const int2*)(mrow1 + c);
            float p0 = fex2(mv0.x ? fmaf(s[nt][0], SCL_L2E, -FIXSHIFT) : MSKVAL);
            float p1 = fex2(mv0.y ? fmaf(s[nt][1], SCL_L2E, -FIXSHIFT) : MSKVAL);
            float p2 = fex2(mv1.x ? fmaf(s[nt][2], SCL_L2E, -FIXSHIFT) : MSKVAL);
            float p3 = fex2(mv1.y ? fmaf(s[nt][3], SCL_L2E, -FIXSHIFT) : MSKVAL);
            lsum0 += p0 + p1;
            lsum1 += p2 + p3;
            uint32_t* pr0 = Ps + r0*SSTR + nt*8;
            uint32_t* pr1 = Ps + (r0+8)*SSTR + nt*8;
            pr0[pw0] = __float_as_uint(p0);  pr0[pw1] = __float_as_uint(p1);
            pr1[pw0] = __float_as_uint(p2);  pr1[pw1] = __float_as_uint(p3);
        }
        __syncwarp();

        // O += P V   (P frags + V frags via LDS.64)
#pragma unroll
        for (int ks = 0; ks < 8; ++ks) {
            const int fo = ks*8 + 2*tig;
            const uint2 plo = *(const uint2*)&Ps[r0*SSTR + fo];
            const uint2 phi = *(const uint2*)&Ps[(r0+8)*SSTR + fo];
            const uint32_t aP[4] = { plo.x, phi.x, plo.y, phi.y };
            const uint32_t* vrow = Vs + (ks*4 + tig)*VSTR;
#pragma unroll
            for (int nt = 0; nt < 8; ++nt) {
                const uint2 vb = *(const uint2*)&vrow[(nt*8+g)*2];
                const uint32_t bf[2] = { vb.x, vb.y };
                mma_tf32(o[nt], aP, bf);
            }
        }
    }

    // row-sum reduction, normalize + write PRE-ROUNDED to g_attn [b,s,h*dh]
    lsum0 += __shfl_xor_sync(0xffffffffu, lsum0, 1);
    lsum0 += __shfl_xor_sync(0xffffffffu, lsum0, 2);
    lsum1 += __shfl_xor_sync(0xffffffffu, lsum1, 1);
    lsum1 += __shfl_xor_sync(0xffffffffu, lsum1, 2);
    const float inv0 = 1.f / lsum0, inv1 = 1.f / lsum1;
    float* out0 = g_attn + ((size_t)b*SEQ + qrow0)*D_MODEL + h*DH;
    float* out1 = out0 + (size_t)8*D_MODEL;
#pragma unroll
    for (int nt = 0; nt < 8; ++nt) {
        const int c = nt*8 + 2*tig;
        float2 v0 = { f2tf32f(o[nt][0]*inv0), f2tf32f(o[nt][1]*inv0) };
        float2 v1 = { f2tf32f(o[nt][2]*inv1), f2tf32f(o[nt][3]*inv1) };
        *(float2*)(out0 + c) = v0;
        *(float2*)(out1 + c) = v1;
    }
}

// ================= launch =================
extern "C" void kernel_launch(void* const* d_in, const int* in_sizes, int n_in,
                              void* d_out, int out_size)
{
    (void)in_sizes; (void)n_in; (void)out_size;
    const float* q  = (const float*)d_in[0];
    const float* k  = (const float*)d_in[1];
    const float* v  = (const float*)d_in[2];
    const int* mask = (const int*)d_in[3];
    const float* Wq = (const float*)d_in[4];
    const float* bq = (const float*)d_in[5];
    const float* Wk = (const float*)d_in[6];
    const float* bk = (const float*)d_in[7];
    const float* Wv = (const float*)d_in[8];
    const float* bv = (const float*)d_in[9];
    const float* Wo = (const float*)d_in[10];
    const float* bo = (const float*)d_in[11];
    float* out = (float*)d_out;

    proj_gemm<<<dim3(D_MODEL/128, MTOT/128, 3), 256>>>(q, k, v, Wq, Wk, Wv, bq, bk, bv);

    cudaFuncSetAttribute(attn_mma, cudaFuncAttributeMaxDynamicSharedMemorySize, ATTN_SMEM_BYTES);
    attn_mma<<<dim3(SEQ/128, NH, BATCH), 256, ATTN_SMEM_BYTES>>>(mask);

    out_gemm<<<dim3(D_MODEL/128, MTOT/128, 1), 256>>>(Wo, bo, out);
}

// round 12
// speedup vs baseline: 1.0847x; 1.0847x over previous
#include <cuda_runtime.h>
#include <cstdint>

#define D_MODEL 1024
#define NH      16
#define DH      64
#define BATCH   2
#define SEQ     2048
#define MTOT    (BATCH*SEQ)   // 4096
#define KDIM    1024

// ---------------- scratch (allocation-free) ----------------
__device__ float g_qh[(size_t)BATCH*NH*SEQ*DH];     // [b,h,s,dh]  tf32-pre-rounded
__device__ float g_kh[(size_t)BATCH*NH*SEQ*DH];
__device__ float g_vh[(size_t)BATCH*NH*SEQ*DH];
__device__ float g_attn[(size_t)BATCH*SEQ*D_MODEL]; // [b,s,h*dh]  tf32-pre-rounded

// =====================================================================
// helpers
// =====================================================================
__device__ __forceinline__ uint32_t f2tf32(float f) {
    uint32_t r;
    asm("cvt.rna.tf32.f32 %0, %1;" : "=r"(r) : "f"(f));
    return r;
}
__device__ __forceinline__ float f2tf32f(float f) { return __uint_as_float(f2tf32(f)); }

// fast exponential: single MUFU.EX2 (2-ulp approx; -20000 -> +0)
__device__ __forceinline__ float fex2(float x) {
    float r;
    asm("ex2.approx.f32 %0, %1;" : "=f"(r) : "f"(x));
    return r;
}

// D += A(16x8,row) * B(8x8,col)  tf32
__device__ __forceinline__ void mma_tf32(float c[4], const uint32_t a[4], const uint32_t b[2]) {
    asm volatile(
        "mma.sync.aligned.m16n8k8.row.col.f32.tf32.tf32.f32 "
        "{%0,%1,%2,%3}, {%4,%5,%6,%7}, {%8,%9}, {%0,%1,%2,%3};"
        : "+f"(c[0]), "+f"(c[1]), "+f"(c[2]), "+f"(c[3])
        : "r"(a[0]), "r"(a[1]), "r"(a[2]), "r"(a[3]), "r"(b[0]), "r"(b[1]));
}

// =====================================================================
// GEMM mainloop (tf32 mma.sync): STS.128 staging, ASTR=44
//   (44·g mod 32 = {0,12,24,4,16,28,8,20} -> +tig covers all banks;
//    rows are 176B -> 16B-aligned vector stores)
// =====================================================================
#define GBK  32
#define ASTR 44

__device__ __forceinline__ void gemm_core(
    const float* __restrict__ gA, const float* __restrict__ gB,
    uint32_t* smA, uint32_t* smB, float acc[2][8][4])
{
    const int tid = threadIdx.x, wid = tid >> 5, lane = tid & 31;
    const int g = lane >> 2, tig = lane & 3;
    const int wm = wid >> 1, wn = wid & 1;

    int srow[4];
    const int scol = (tid & 7) * 4;
#pragma unroll
    for (int r = 0; r < 4; ++r) srow[r] = (tid + r*256) >> 3;

    float4 pa[4], pb[4];
#pragma unroll
    for (int r = 0; r < 4; ++r) {
        pa[r] = *(const float4*)(gA + (size_t)srow[r]*KDIM + scol);
        pb[r] = *(const float4*)(gB + (size_t)srow[r]*KDIM + scol);
    }

    const int NKT = KDIM / GBK;   // 32
    for (int kt = 0; kt < NKT; ++kt) {
        __syncthreads();
#pragma unroll
        for (int r = 0; r < 4; ++r) {
            const uint4 va = make_uint4(f2tf32(pa[r].x), f2tf32(pa[r].y), f2tf32(pa[r].z), f2tf32(pa[r].w));
            const uint4 vb = make_uint4(f2tf32(pb[r].x), f2tf32(pb[r].y), f2tf32(pb[r].z), f2tf32(pb[r].w));
            *(uint4*)(smA + srow[r]*ASTR + scol) = va;
            *(uint4*)(smB + srow[r]*ASTR + scol) = vb;
        }
        __syncthreads();
        if (kt + 1 < NKT) {
            const int k1 = (kt + 1) * GBK;
#pragma unroll
            for (int r = 0; r < 4; ++r) {
                pa[r] = *(const float4*)(gA + (size_t)srow[r]*KDIM + k1 + scol);
                pb[r] = *(const float4*)(gB + (size_t)srow[r]*KDIM + k1 + scol);
            }
        }
#pragma unroll
        for (int ks = 0; ks < 4; ++ks) {
            uint32_t af[2][4];
#pragma unroll
            for (int mt = 0; mt < 2; ++mt) {
                const int mr = wm*32 + mt*16 + g;
                af[mt][0] = smA[mr*ASTR     + ks*8 + tig];
                af[mt][1] = smA[(mr+8)*ASTR + ks*8 + tig];
                af[mt][2] = smA[mr*ASTR     + ks*8 + tig + 4];
                af[mt][3] = smA[(mr+8)*ASTR + ks*8 + tig + 4];
            }
#pragma unroll
            for (int nt = 0; nt < 8; ++nt) {
                const int nr = wn*64 + nt*8 + g;
                uint32_t bf[2];
                bf[0] = smB[nr*ASTR + ks*8 + tig];
                bf[1] = smB[nr*ASTR + ks*8 + tig + 4];
                mma_tf32(acc[0][nt], af[0], bf);
                mma_tf32(acc[1][nt], af[1], bf);
            }
        }
    }
}

// ---- fused Q/K/V projection (grid.z selects), scatter to head layout ----
__global__ __launch_bounds__(256, 2) void proj_gemm(
    const float* __restrict__ xq, const float* __restrict__ xk, const float* __restrict__ xv,
    const float* __restrict__ Wq, const float* __restrict__ Wk, const float* __restrict__ Wv,
    const float* __restrict__ bq, const float* __restrict__ bk, const float* __restrict__ bv)
{
    __shared__ uint32_t smA[128*ASTR];
    __shared__ uint32_t smB[128*ASTR];
    const int z = blockIdx.z;
    const float* X    = (z == 0) ? xq : (z == 1) ? xk : xv;
    const float* W    = (z == 0) ? Wq : (z == 1) ? Wk : Wv;
    const float* bias = (z == 0) ? bq : (z == 1) ? bk : bv;
    float* out        = (z == 0) ? g_qh : (z == 1) ? g_kh : g_vh;

    const int m0 = blockIdx.y * 128, n0 = blockIdx.x * 128;
    float acc[2][8][4] = {};
    gemm_core(X + (size_t)m0*KDIM, W + (size_t)n0*KDIM, smA, smB, acc);

    const int tid = threadIdx.x, wid = tid >> 5, lane = tid & 31;
    const int g = lane >> 2, tig = lane & 3;
    const int wm = wid >> 1, wn = wid & 1;
#pragma unroll
    for (int mt = 0; mt < 2; ++mt) {
        const int m = m0 + wm*32 + mt*16 + g;
        const int bi = m >> 11, s = m & (SEQ - 1);
#pragma unroll
        for (int nt = 0; nt < 8; ++nt) {
            const int n = n0 + wn*64 + nt*8 + 2*tig;
            const float2 bv2 = *(const float2*)(bias + n);
            float2 v0 = { f2tf32f(acc[mt][nt][0] + bv2.x), f2tf32f(acc[mt][nt][1] + bv2.y) };
            float2 v1 = { f2tf32f(acc[mt][nt][2] + bv2.x), f2tf32f(acc[mt][nt][3] + bv2.y) };
            const int h = n >> 6, d = n & 63;
            float* base = out + (((size_t)bi*NH + h)*SEQ) * DH + d;
            *(float2*)(base + (size_t)s*DH)     = v0;
            *(float2*)(base + (size_t)(s+8)*DH) = v1;
        }
    }
}

// ---- output projection: d_out = g_attn @ Wo^T + bo ----
__global__ __launch_bounds__(256, 2) void out_gemm(
    const float* __restrict__ Wo, const float* __restrict__ bo, float* __restrict__ out)
{
    __shared__ uint32_t smA[128*ASTR];
    __shared__ uint32_t smB[128*ASTR];
    const int m0 = blockIdx.y * 128, n0 = blockIdx.x * 128;
    float acc[2][8][4] = {};
    gemm_core(g_attn + (size_t)m0*KDIM, Wo + (size_t)n0*KDIM, smA, smB, acc);

    const int tid = threadIdx.x, wid = tid >> 5, lane = tid & 31;
    const int g = lane >> 2, tig = lane & 3;
    const int wm = wid >> 1, wn = wid & 1;
#pragma unroll
    for (int mt = 0; mt < 2; ++mt) {
        const int m = m0 + wm*32 + mt*16 + g;
#pragma unroll
        for (int nt = 0; nt < 8; ++nt) {
            const int n = n0 + wn*64 + nt*8 + 2*tig;
            const float2 bv2 = *(const float2*)(bo + n);
            float2 v0 = { acc[mt][nt][0] + bv2.x, acc[mt][nt][1] + bv2.y };
            float2 v1 = { acc[mt][nt][2] + bv2.x, acc[mt][nt][3] + bv2.y };
            *(float2*)(out + (size_t)m*D_MODEL + n)     = v0;
            *(float2*)(out + (size_t)(m+8)*D_MODEL + n) = v1;
        }
    }
}

// =====================================================================
// Flash attention: round-10 winner + raw-fp32 P store (no cvt on P path)
//   smem: Qs[128][68], Ks[64][68], Vs[64][72], Ps[128][68]
// =====================================================================
#define QSTR 68
#define VSTR 72
#define KS_OFFW (128*QSTR)
#define VS_OFFW (KS_OFFW + 64*QSTR)
#define PS_OFFW (VS_OFFW + 64*VSTR)
#define ATTN_SMEM_BYTES ((PS_OFFW + 128*QSTR) * 4)
#define LOG2E    1.4426950408889634f
#define SCL_L2E  (0.125f * LOG2E)
#define FIXSHIFT 16.0f
#define MSKVAL   (-20000.0f)

__global__ __launch_bounds__(256, 2) void attn_mma(const int* __restrict__ mask)
{
    extern __shared__ uint32_t sm[];
    uint32_t* Qs = sm;                  // [128][68]
    uint32_t* Ks = sm + KS_OFFW;        // [64][68]
    uint32_t* Vs = sm + VS_OFFW;        // [64][72]
    uint32_t* Ps = sm + PS_OFFW;        // [128][68]

    const int qt = blockIdx.x, h = blockIdx.y, b = blockIdx.z;
    const int tid = threadIdx.x, wid = tid >> 5, lane = tid & 31;
    const int g = lane >> 2, tig = lane & 3;

    const size_t bh = ((size_t)b*NH + h)*SEQ*DH;
    const uint32_t* Qg = (const uint32_t*)g_qh + bh + (size_t)qt*128*DH;
    const uint32_t* Kg = (const uint32_t*)g_kh + bh;
    const uint32_t* Vg = (const uint32_t*)g_vh + bh;

    // stage Q raw (pre-rounded): 2048 uint4 slots / 256 thr = 8 each
#pragma unroll
    for (int r = 0; r < 8; ++r) {
        const int slot = tid + r*256;
        const int row = slot >> 4, c4 = (slot & 15) * 4;
        *(uint4*)&Qs[row*QSTR + c4] = *(const uint4*)(Qg + (size_t)row*DH + c4);
    }

    const int r0 = wid*16 + g;
    float lsum0 = 0.f, lsum1 = 0.f;   // lane-local partial row sums
    float o[8][4];
#pragma unroll
    for (int nt = 0; nt < 8; ++nt)
#pragma unroll
        for (int i = 0; i < 4; ++i) o[nt][i] = 0.f;

    const int qrow0 = qt*128 + r0;
    const int* mrow0 = mask + ((size_t)b*SEQ + qrow0)*SEQ;
    const int* mrow1 = mrow0 + 8*SEQ;

    // per-thread staging slots (4 rows of the kv tile)
    int krow[4];
    const int kc0 = (tid & 15) * 4;
#pragma unroll
    for (int r = 0; r < 4; ++r) krow[r] = (tid + r*256) >> 4;

    // prefetch kv tile 0 (raw bits)
    uint4 pk[4], pv[4];
#pragma unroll
    for (int r = 0; r < 4; ++r) {
        pk[r] = *(const uint4*)(Kg + (size_t)krow[r]*DH + kc0);
        pv[r] = *(const uint4*)(Vg + (size_t)krow[r]*DH + kc0);
    }

    const int NT = SEQ/64;
    for (int kt = 0; kt < NT; ++kt) {
        __syncthreads();   // prev tile fully consumed (and Q staged on kt=0)
        // store prefetched K,V tile to smem (raw STS.128)
#pragma unroll
        for (int r = 0; r < 4; ++r) {
            *(uint4*)&Ks[krow[r]*QSTR + kc0] = pk[r];
            *(uint4*)&Vs[krow[r]*VSTR + kc0] = pv[r];
        }
        __syncthreads();
        if (kt + 1 < NT) {
            const uint32_t* Kn = Kg + (size_t)(kt+1)*64*DH;
            const uint32_t* Vn = Vg + (size_t)(kt+1)*64*DH;
#pragma unroll
            for (int r = 0; r < 4; ++r) {
                pk[r] = *(const uint4*)(Kn + (size_t)krow[r]*DH + kc0);
                pv[r] = *(const uint4*)(Vn + (size_t)krow[r]*DH + kc0);
            }
        }

        // S = Q K^T  (16 rows x 64 keys per warp)
        float s[8][4];
#pragma unroll
        for (int nt = 0; nt < 8; ++nt) { s[nt][0]=0.f; s[nt][1]=0.f; s[nt][2]=0.f; s[nt][3]=0.f; }
#pragma unroll
        for (int ks = 0; ks < 8; ++ks) {
            uint32_t aQ[4];
            aQ[0] = Qs[r0*QSTR     + ks*8 + tig];
            aQ[1] = Qs[(r0+8)*QSTR + ks*8 + tig];
            aQ[2] = Qs[r0*QSTR     + ks*8 + tig + 4];
            aQ[3] = Qs[(r0+8)*QSTR + ks*8 + tig + 4];
#pragma unroll
            for (int nt = 0; nt < 8; ++nt) {
                uint32_t bf[2];
                bf[0] = Ks[(nt*8+g)*QSTR + ks*8 + tig];
                bf[1] = Ks[(nt*8+g)*QSTR + ks*8 + tig + 4];
                mma_tf32(s[nt], aQ, bf);
            }
        }

        // mask + fixed-shift MUFU ex2; lane-local sums; P -> smem RAW fp32
#pragma unroll
        for (int nt = 0; nt < 8; ++nt) {
            const int c = kt*64 + nt*8 + 2*tig;
            const int2 mv0 = *(const int2*)(mrow0 + c);
            const int2 mv1 = *(const int2*)(mrow1 + c);
            float p0 = fex2(mv0.x ? fmaf(s[nt][0], SCL_L2E, -FIXSHIFT) : MSKVAL);
            float p1 = fex2(mv0.y ? fmaf(s[nt][1], SCL_L2E, -FIXSHIFT) : MSKVAL);
            float p2 = fex2(mv1.x ? fmaf(s[nt][2], SCL_L2E, -FIXSHIFT) : MSKVAL);
            float p3 = fex2(mv1.y ? fmaf(s[nt][3], SCL_L2E, -FIXSHIFT) : MSKVAL);
            lsum0 += p0 + p1;
            lsum1 += p2 + p3;
            const int cc = nt*8 + 2*tig;
            Ps[r0*QSTR + cc]         = __float_as_uint(p0);
            Ps[r0*QSTR + cc + 1]     = __float_as_uint(p1);
            Ps[(r0+8)*QSTR + cc]     = __float_as_uint(p2);
            Ps[(r0+8)*QSTR + cc + 1] = __float_as_uint(p3);
        }
        __syncwarp();

        // O += P V
#pragma unroll
        for (int ks = 0; ks < 8; ++ks) {
            uint32_t aP[4];
            aP[0] = Ps[r0*QSTR     + ks*8 + tig];
            aP[1] = Ps[(r0+8)*QSTR + ks*8 + tig];
            aP[2] = Ps[r0*QSTR     + ks*8 + tig + 4];
            aP[3] = Ps[(r0+8)*QSTR + ks*8 + tig + 4];
#pragma unroll
            for (int nt = 0; nt < 8; ++nt) {
                uint32_t bf[2];
                bf[0] = Vs[(ks*8+tig)*VSTR   + nt*8 + g];
                bf[1] = Vs[(ks*8+tig+4)*VSTR + nt*8 + g];
                mma_tf32(o[nt], aP, bf);
            }
        }
    }

    // row-sum reduction, normalize + write PRE-ROUNDED to g_attn [b,s,h*dh]
    lsum0 += __shfl_xor_sync(0xffffffffu, lsum0, 1);
    lsum0 += __shfl_xor_sync(0xffffffffu, lsum0, 2);
    lsum1 += __shfl_xor_sync(0xffffffffu, lsum1, 1);
    lsum1 += __shfl_xor_sync(0xffffffffu, lsum1, 2);
    const float inv0 = 1.f / lsum0, inv1 = 1.f / lsum1;
    float* out0 = g_attn + ((size_t)b*SEQ + qrow0)*D_MODEL + h*DH;
    float* out1 = out0 + (size_t)8*D_MODEL;
#pragma unroll
    for (int nt = 0; nt < 8; ++nt) {
        const int c = nt*8 + 2*tig;
        float2 v0 = { f2tf32f(o[nt][0]*inv0), f2tf32f(o[nt][1]*inv0) };
        float2 v1 = { f2tf32f(o[nt][2]*inv1), f2tf32f(o[nt][3]*inv1) };
        *(float2*)(out0 + c) = v0;
        *(float2*)(out1 + c) = v1;
    }
}

// ================= launch =================
extern "C" void kernel_launch(void* const* d_in, const int* in_sizes, int n_in,
                              void* d_out, int out_size)
{
    (void)in_sizes; (void)n_in; (void)out_size;
    const float* q  = (const float*)d_in[0];
    const float* k  = (const float*)d_in[1];
    const float* v  = (const float*)d_in[2];
    const int* mask = (const int*)d_in[3];
    const float* Wq = (const float*)d_in[4];
    const float* bq = (const float*)d_in[5];
    const float* Wk = (const float*)d_in[6];
    const float* bk = (const float*)d_in[7];
    const float* Wv = (const float*)d_in[8];
    const float* bv = (const float*)d_in[9];
    const float* Wo = (const float*)d_in[10];
    const float* bo = (const float*)d_in[11];
    float* out = (float*)d_out;

    proj_gemm<<<dim3(D_MODEL/128, MTOT/128, 3), 256>>>(q, k, v, Wq, Wk, Wv, bq, bk, bv);

    cudaFuncSetAttribute(attn_mma, cudaFuncAttributeMaxDynamicSharedMemorySize, ATTN_SMEM_BYTES);
    attn_mma<<<dim3(SEQ/128, NH, BATCH), 256, ATTN_SMEM_BYTES>>>(mask);

    out_gemm<<<dim3(D_MODEL/128, MTOT/128, 1), 256>>>(Wo, bo, out);
}

// round 13
// speedup vs baseline: 1.1465x; 1.0569x over previous
#include <cuda_runtime.h>
#include <cstdint>

#define D_MODEL 1024
#define NH      16
#define DH      64
#define BATCH   2
#define SEQ     2048
#define MTOT    (BATCH*SEQ)   // 4096
#define KDIM    1024

// ---------------- scratch (allocation-free) ----------------
__device__ float g_qh[(size_t)BATCH*NH*SEQ*DH];     // [b,h,s,dh]  tf32-pre-rounded
__device__ float g_kh[(size_t)BATCH*NH*SEQ*DH];
__device__ float g_vh[(size_t)BATCH*NH*SEQ*DH];
__device__ float g_attn[(size_t)BATCH*SEQ*D_MODEL]; // [b,s,h*dh]  tf32-pre-rounded

// =====================================================================
// helpers
// =====================================================================
__device__ __forceinline__ uint32_t f2tf32(float f) {
    uint32_t r;
    asm("cvt.rna.tf32.f32 %0, %1;" : "=r"(r) : "f"(f));
    return r;
}
__device__ __forceinline__ float f2tf32f(float f) { return __uint_as_float(f2tf32(f)); }

// fast exponential: single MUFU.EX2 (2-ulp approx; -20000 -> +0)
__device__ __forceinline__ float fex2(float x) {
    float r;
    asm("ex2.approx.f32 %0, %1;" : "=f"(r) : "f"(x));
    return r;
}

// D += A(16x8,row) * B(8x8,col)  tf32
__device__ __forceinline__ void mma_tf32(float c[4], const uint32_t a[4], const uint32_t b[2]) {
    asm volatile(
        "mma.sync.aligned.m16n8k8.row.col.f32.tf32.tf32.f32 "
        "{%0,%1,%2,%3}, {%4,%5,%6,%7}, {%8,%9}, {%0,%1,%2,%3};"
        : "+f"(c[0]), "+f"(c[1]), "+f"(c[2]), "+f"(c[3])
        : "r"(a[0]), "r"(a[1]), "r"(a[2]), "r"(a[3]), "r"(b[0]), "r"(b[1]));
}

// =====================================================================
// GEMM mainloop (tf32 mma.sync), 2-stage smem double buffer:
//   ONE __syncthreads per K-step (33 barriers vs 64).
//   iter kt: store prefetched tile kt+1 -> other stage, prefetch kt+2,
//            compute from current stage, sync.
//   dyn smem: [stage][A|B][128*ASTR] = 72 KB -> 2 CTAs/SM.
// =====================================================================
#define GBK   32
#define ASTR  36                 // BK + 4 pad (proven conflict-free)
#define TILEW (128*ASTR)         // words per A or B tile
#define GEMM_SMEM_BYTES (2*2*TILEW*4)

__device__ __forceinline__ void gemm_stage(
    uint32_t* dstA, uint32_t* dstB, const float4 pa[4], const float4 pb[4],
    const int srow[4], int scol)
{
#pragma unroll
    for (int r = 0; r < 4; ++r) {
        uint32_t* pA = dstA + srow[r]*ASTR + scol;
        pA[0]=f2tf32(pa[r].x); pA[1]=f2tf32(pa[r].y); pA[2]=f2tf32(pa[r].z); pA[3]=f2tf32(pa[r].w);
        uint32_t* pB = dstB + srow[r]*ASTR + scol;
        pB[0]=f2tf32(pb[r].x); pB[1]=f2tf32(pb[r].y); pB[2]=f2tf32(pb[r].z); pB[3]=f2tf32(pb[r].w);
    }
}

__device__ __forceinline__ void gemm_core(
    const float* __restrict__ gA, const float* __restrict__ gB,
    uint32_t* smg, float acc[2][8][4])
{
    const int tid = threadIdx.x, wid = tid >> 5, lane = tid & 31;
    const int g = lane >> 2, tig = lane & 3;
    const int wm = wid >> 1, wn = wid & 1;

    int srow[4];
    const int scol = (tid & 7) * 4;
#pragma unroll
    for (int r = 0; r < 4; ++r) srow[r] = (tid + r*256) >> 3;

    float4 pa[4], pb[4];
    // prologue: tile 0 -> stage 0
#pragma unroll
    for (int r = 0; r < 4; ++r) {
        pa[r] = *(const float4*)(gA + (size_t)srow[r]*KDIM + scol);
        pb[r] = *(const float4*)(gB + (size_t)srow[r]*KDIM + scol);
    }
    gemm_stage(smg, smg + TILEW, pa, pb, srow, scol);
    // prefetch tile 1
#pragma unroll
    for (int r = 0; r < 4; ++r) {
        pa[r] = *(const float4*)(gA + (size_t)srow[r]*KDIM + GBK + scol);
        pb[r] = *(const float4*)(gB + (size_t)srow[r]*KDIM + GBK + scol);
    }
    __syncthreads();

    const int NKT = KDIM / GBK;   // 32
    for (int kt = 0; kt < NKT; ++kt) {
        const int cur = kt & 1, nxt = cur ^ 1;
        // store prefetched tile kt+1 into the other stage
        if (kt + 1 < NKT)
            gemm_stage(smg + nxt*2*TILEW, smg + nxt*2*TILEW + TILEW, pa, pb, srow, scol);
        // prefetch tile kt+2
        if (kt + 2 < NKT) {
            const int k2 = (kt + 2) * GBK;
#pragma unroll
            for (int r = 0; r < 4; ++r) {
                pa[r] = *(const float4*)(gA + (size_t)srow[r]*KDIM + k2 + scol);
                pb[r] = *(const float4*)(gB + (size_t)srow[r]*KDIM + k2 + scol);
            }
        }
        // compute from current stage
        const uint32_t* smA = smg + cur*2*TILEW;
        const uint32_t* smB = smA + TILEW;
#pragma unroll
        for (int ks = 0; ks < 4; ++ks) {
            uint32_t af[2][4];
#pragma unroll
            for (int mt = 0; mt < 2; ++mt) {
                const int mr = wm*32 + mt*16 + g;
                af[mt][0] = smA[mr*ASTR     + ks*8 + tig];
                af[mt][1] = smA[(mr+8)*ASTR + ks*8 + tig];
                af[mt][2] = smA[mr*ASTR     + ks*8 + tig + 4];
                af[mt][3] = smA[(mr+8)*ASTR + ks*8 + tig + 4];
            }
#pragma unroll
            for (int nt = 0; nt < 8; ++nt) {
                const int nr = wn*64 + nt*8 + g;
                uint32_t bf[2];
                bf[0] = smB[nr*ASTR + ks*8 + tig];
                bf[1] = smB[nr*ASTR + ks*8 + tig + 4];
                mma_tf32(acc[0][nt], af[0], bf);
                mma_tf32(acc[1][nt], af[1], bf);
            }
        }
        __syncthreads();
    }
}

// ---- fused Q/K/V projection (grid.z selects), scatter to head layout ----
__global__ __launch_bounds__(256, 2) void proj_gemm(
    const float* __restrict__ xq, const float* __restrict__ xk, const float* __restrict__ xv,
    const float* __restrict__ Wq, const float* __restrict__ Wk, const float* __restrict__ Wv,
    const float* __restrict__ bq, const float* __restrict__ bk, const float* __restrict__ bv)
{
    extern __shared__ uint32_t smg[];
    const int z = blockIdx.z;
    const float* X    = (z == 0) ? xq : (z == 1) ? xk : xv;
    const float* W    = (z == 0) ? Wq : (z == 1) ? Wk : Wv;
    const float* bias = (z == 0) ? bq : (z == 1) ? bk : bv;
    float* out        = (z == 0) ? g_qh : (z == 1) ? g_kh : g_vh;

    const int m0 = blockIdx.y * 128, n0 = blockIdx.x * 128;
    float acc[2][8][4] = {};
    gemm_core(X + (size_t)m0*KDIM, W + (size_t)n0*KDIM, smg, acc);

    const int tid = threadIdx.x, wid = tid >> 5, lane = tid & 31;
    const int g = lane >> 2, tig = lane & 3;
    const int wm = wid >> 1, wn = wid & 1;
#pragma unroll
    for (int mt = 0; mt < 2; ++mt) {
        const int m = m0 + wm*32 + mt*16 + g;
        const int bi = m >> 11, s = m & (SEQ - 1);
#pragma unroll
        for (int nt = 0; nt < 8; ++nt) {
            const int n = n0 + wn*64 + nt*8 + 2*tig;
            const float2 bv2 = *(const float2*)(bias + n);
            float2 v0 = { f2tf32f(acc[mt][nt][0] + bv2.x), f2tf32f(acc[mt][nt][1] + bv2.y) };
            float2 v1 = { f2tf32f(acc[mt][nt][2] + bv2.x), f2tf32f(acc[mt][nt][3] + bv2.y) };
            const int h = n >> 6, d = n & 63;
            float* base = out + (((size_t)bi*NH + h)*SEQ) * DH + d;
            *(float2*)(base + (size_t)s*DH)     = v0;
            *(float2*)(base + (size_t)(s+8)*DH) = v1;
        }
    }
}

// ---- output projection: d_out = g_attn @ Wo^T + bo ----
__global__ __launch_bounds__(256, 2) void out_gemm(
    const float* __restrict__ Wo, const float* __restrict__ bo, float* __restrict__ out)
{
    extern __shared__ uint32_t smg[];
    const int m0 = blockIdx.y * 128, n0 = blockIdx.x * 128;
    float acc[2][8][4] = {};
    gemm_core(g_attn + (size_t)m0*KDIM, Wo + (size_t)n0*KDIM, smg, acc);

    const int tid = threadIdx.x, wid = tid >> 5, lane = tid & 31;
    const int g = lane >> 2, tig = lane & 3;
    const int wm = wid >> 1, wn = wid & 1;
#pragma unroll
    for (int mt = 0; mt < 2; ++mt) {
        const int m = m0 + wm*32 + mt*16 + g;
#pragma unroll
        for (int nt = 0; nt < 8; ++nt) {
            const int n = n0 + wn*64 + nt*8 + 2*tig;
            const float2 bv2 = *(const float2*)(bo + n);
            float2 v0 = { acc[mt][nt][0] + bv2.x, acc[mt][nt][1] + bv2.y };
            float2 v1 = { acc[mt][nt][2] + bv2.x, acc[mt][nt][3] + bv2.y };
            *(float2*)(out + (size_t)m*D_MODEL + n)     = v0;
            *(float2*)(out + (size_t)(m+8)*D_MODEL + n) = v1;
        }
    }
}

// =====================================================================
// Flash attention — round-10 winner, byte-identical
//   smem: Qs[128][68], Ks[64][68], Vs[64][72], Ps[128][68]
// =====================================================================
#define QSTR 68
#define VSTR 72
#define KS_OFFW (128*QSTR)
#define VS_OFFW (KS_OFFW + 64*QSTR)
#define PS_OFFW (VS_OFFW + 64*VSTR)
#define ATTN_SMEM_BYTES ((PS_OFFW + 128*QSTR) * 4)
#define LOG2E    1.4426950408889634f
#define SCL_L2E  (0.125f * LOG2E)
#define FIXSHIFT 16.0f
#define MSKVAL   (-20000.0f)

__global__ __launch_bounds__(256, 2) void attn_mma(const int* __restrict__ mask)
{
    extern __shared__ uint32_t sm[];
    uint32_t* Qs = sm;                  // [128][68]
    uint32_t* Ks = sm + KS_OFFW;        // [64][68]
    uint32_t* Vs = sm + VS_OFFW;        // [64][72]
    uint32_t* Ps = sm + PS_OFFW;        // [128][68]

    const int qt = blockIdx.x, h = blockIdx.y, b = blockIdx.z;
    const int tid = threadIdx.x, wid = tid >> 5, lane = tid & 31;
    const int g = lane >> 2, tig = lane & 3;

    const size_t bh = ((size_t)b*NH + h)*SEQ*DH;
    const uint32_t* Qg = (const uint32_t*)g_qh + bh + (size_t)qt*128*DH;
    const uint32_t* Kg = (const uint32_t*)g_kh + bh;
    const uint32_t* Vg = (const uint32_t*)g_vh + bh;

    // stage Q raw (pre-rounded): 2048 uint4 slots / 256 thr = 8 each
#pragma unroll
    for (int r = 0; r < 8; ++r) {
        const int slot = tid + r*256;
        const int row = slot >> 4, c4 = (slot & 15) * 4;
        *(uint4*)&Qs[row*QSTR + c4] = *(const uint4*)(Qg + (size_t)row*DH + c4);
    }

    const int r0 = wid*16 + g;
    float lsum0 = 0.f, lsum1 = 0.f;   // lane-local partial row sums
    float o[8][4];
#pragma unroll
    for (int nt = 0; nt < 8; ++nt)
#pragma unroll
        for (int i = 0; i < 4; ++i) o[nt][i] = 0.f;

    const int qrow0 = qt*128 + r0;
    const int* mrow0 = mask + ((size_t)b*SEQ + qrow0)*SEQ;
    const int* mrow1 = mrow0 + 8*SEQ;

    // per-thread staging slots (4 rows of the kv tile)
    int krow[4];
    const int kc0 = (tid & 15) * 4;
#pragma unroll
    for (int r = 0; r < 4; ++r) krow[r] = (tid + r*256) >> 4;

    // prefetch kv tile 0 (raw bits)
    uint4 pk[4], pv[4];
#pragma unroll
    for (int r = 0; r < 4; ++r) {
        pk[r] = *(const uint4*)(Kg + (size_t)krow[r]*DH + kc0);
        pv[r] = *(const uint4*)(Vg + (size_t)krow[r]*DH + kc0);
    }

    const int NT = SEQ/64;
    for (int kt = 0; kt < NT; ++kt) {
        __syncthreads();   // prev tile fully consumed (and Q staged on kt=0)
        // store prefetched K,V tile to smem (raw STS.128)
#pragma unroll
        for (int r = 0; r < 4; ++r) {
            *(uint4*)&Ks[krow[r]*QSTR + kc0] = pk[r];
            *(uint4*)&Vs[krow[r]*VSTR + kc0] = pv[r];
        }
        __syncthreads();
        if (kt + 1 < NT) {
            const uint32_t* Kn = Kg + (size_t)(kt+1)*64*DH;
            const uint32_t* Vn = Vg + (size_t)(kt+1)*64*DH;
#pragma unroll
            for (int r = 0; r < 4; ++r) {
                pk[r] = *(const uint4*)(Kn + (size_t)krow[r]*DH + kc0);
                pv[r] = *(const uint4*)(Vn + (size_t)krow[r]*DH + kc0);
            }
        }

        // S = Q K^T  (16 rows x 64 keys per warp)
        float s[8][4];
#pragma unroll
        for (int nt = 0; nt < 8; ++nt) { s[nt][0]=0.f; s[nt][1]=0.f; s[nt][2]=0.f; s[nt][3]=0.f; }
#pragma unroll
        for (int ks = 0; ks < 8; ++ks) {
            uint32_t aQ[4];
            aQ[0] = Qs[r0*QSTR     + ks*8 + tig];
            aQ[1] = Qs[(r0+8)*QSTR + ks*8 + tig];
            aQ[2] = Qs[r0*QSTR     + ks*8 + tig + 4];
            aQ[3] = Qs[(r0+8)*QSTR + ks*8 + tig + 4];
#pragma unroll
            for (int nt = 0; nt < 8; ++nt) {
                uint32_t bf[2];
                bf[0] = Ks[(nt*8+g)*QSTR + ks*8 + tig];
                bf[1] = Ks[(nt*8+g)*QSTR + ks*8 + tig + 4];
                mma_tf32(s[nt], aQ, bf);
            }
        }

        // mask + fixed-shift MUFU ex2; lane-local sums; P -> smem (rna-rounded)
#pragma unroll
        for (int nt = 0; nt < 8; ++nt) {
            const int c = kt*64 + nt*8 + 2*tig;
            const int2 mv0 = *(const int2*)(mrow0 + c);
            const int2 mv1 = *(const int2*)(mrow1 + c);
            float p0 = fex2(mv0.x ? fmaf(s[nt][0], SCL_L2E, -FIXSHIFT) : MSKVAL);
            float p1 = fex2(mv0.y ? fmaf(s[nt][1], SCL_L2E, -FIXSHIFT) : MSKVAL);
            float p2 = fex2(mv1.x ? fmaf(s[nt][2], SCL_L2E, -FIXSHIFT) : MSKVAL);
            float p3 = fex2(mv1.y ? fmaf(s[nt][3], SCL_L2E, -FIXSHIFT) : MSKVAL);
            lsum0 += p0 + p1;
            lsum1 += p2 + p3;
            const int cc = nt*8 + 2*tig;
            Ps[r0*QSTR + cc]         = f2tf32(p0);
            Ps[r0*QSTR + cc + 1]     = f2tf32(p1);
            Ps[(r0+8)*QSTR + cc]     = f2tf32(p2);
            Ps[(r0+8)*QSTR + cc + 1] = f2tf32(p3);
        }
        __syncwarp();

        // O += P V
#pragma unroll
        for (int ks = 0; ks < 8; ++ks) {
            uint32_t aP[4];
            aP[0] = Ps[r0*QSTR     + ks*8 + tig];
            aP[1] = Ps[(r0+8)*QSTR + ks*8 + tig];
            aP[2] = Ps[r0*QSTR     + ks*8 + tig + 4];
            aP[3] = Ps[(r0+8)*QSTR + ks*8 + tig + 4];
#pragma unroll
            for (int nt = 0; nt < 8; ++nt) {
                uint32_t bf[2];
                bf[0] = Vs[(ks*8+tig)*VSTR   + nt*8 + g];
                bf[1] = Vs[(ks*8+tig+4)*VSTR + nt*8 + g];
                mma_tf32(o[nt], aP, bf);
            }
        }
    }

    // row-sum reduction, normalize + write PRE-ROUNDED to g_attn [b,s,h*dh]
    lsum0 += __shfl_xor_sync(0xffffffffu, lsum0, 1);
    lsum0 += __shfl_xor_sync(0xffffffffu, lsum0, 2);
    lsum1 += __shfl_xor_sync(0xffffffffu, lsum1, 1);
    lsum1 += __shfl_xor_sync(0xffffffffu, lsum1, 2);
    const float inv0 = 1.f / lsum0, inv1 = 1.f / lsum1;
    float* out0 = g_attn + ((size_t)b*SEQ + qrow0)*D_MODEL + h*DH;
    float* out1 = out0 + (size_t)8*D_MODEL;
#pragma unroll
    for (int nt = 0; nt < 8; ++nt) {
        const int c = nt*8 + 2*tig;
        float2 v0 = { f2tf32f(o[nt][0]*inv0), f2tf32f(o[nt][1]*inv0) };
        float2 v1 = { f2tf32f(o[nt][2]*inv1), f2tf32f(o[nt][3]*inv1) };
        *(float2*)(out0 + c) = v0;
        *(float2*)(out1 + c) = v1;
    }
}

// ================= launch =================
extern "C" void kernel_launch(void* const* d_in, const int* in_sizes, int n_in,
                              void* d_out, int out_size)
{
    (void)in_sizes; (void)n_in; (void)out_size;
    const float* q  = (const float*)d_in[0];
    const float* k  = (const float*)d_in[1];
    const float* v  = (const float*)d_in[2];
    const int* mask = (const int*)d_in[3];
    const float* Wq = (const float*)d_in[4];
    const float* bq = (const float*)d_in[5];
    const float* Wk = (const float*)d_in[6];
    const float* bk = (const float*)d_in[7];
    const float* Wv = (const float*)d_in[8];
    const float* bv = (const float*)d_in[9];
    const float* Wo = (const float*)d_in[10];
    const float* bo = (const float*)d_in[11];
    float* out = (float*)d_out;

    cudaFuncSetAttribute(proj_gemm, cudaFuncAttributeMaxDynamicSharedMemorySize, GEMM_SMEM_BYTES);
    cudaFuncSetAttribute(out_gemm,  cudaFuncAttributeMaxDynamicSharedMemorySize, GEMM_SMEM_BYTES);
    cudaFuncSetAttribute(attn_mma,  cudaFuncAttributeMaxDynamicSharedMemorySize, ATTN_SMEM_BYTES);

    proj_gemm<<<dim3(D_MODEL/128, MTOT/128, 3), 256, GEMM_SMEM_BYTES>>>(q, k, v, Wq, Wk, Wv, bq, bk, bv);
    attn_mma<<<dim3(SEQ/128, NH, BATCH), 256, ATTN_SMEM_BYTES>>>(mask);
    out_gemm<<<dim3(D_MODEL/128, MTOT/128, 1), 256, GEMM_SMEM_BYTES>>>(Wo, bo, out);
}